// round 11
// baseline (speedup 1.0000x reference)
#include <cuda_runtime.h>
#include <cuda_fp16.h>
#include <stdint.h>

// ---------------------------------------------------------------------------
// Bidirectional GRU w/ predictor feedback. B=128, T=1024, H=512.
// Persistent grid: 128 CTAs (64/dir), 384 thr, ~182KB SMEM (1 CTA/SM).
// C[128b x 32n] = h[128x512] @ W[32x512]^T via mma.sync m16n8k16 fp16.
// Warps 0-3: MMA. Warps 4-11: stage K-chunks + epilogue.
// R11: (1) per-chunk h counters -- staging chunk kc waits only on its 16
// producer CTAs (skew absorbed into the chunk pipeline); (2) spart exchange
// is a running-sum red.add.f32 into one accumulator per (dir,b) -- consumer
// reads ONE float and differences against a register (no gather, no zeroing);
// (3) x/mask prefetch ahead of staging.
// ---------------------------------------------------------------------------

namespace {
constexpr int kB = 128;
constexpr int kT = 1024;
constexpr int kH = 512;
constexpr int kCtaPerDir = 64;
constexpr int kNCta = 2 * kCtaPerDir;
constexpr int kThreads = 384;

// SMEM layout (bytes). Word strides % 32 == 4 -> conflict-free.
constexpr int kWStride = 520;                    // fp16 per W row (512+8)
constexpr int kWBytes = 32 * kWStride * 2;       // 33280
constexpr int kABase = kWBytes;
constexpr int kARow = 272;                       // bytes per A row (128k fp16 + pad)
constexpr int kAPart = kB * kARow;               // 34816
constexpr int kGhs = kABase + 4 * kAPart;        // 172544  ([24][132] f32)
constexpr int kGhsStride = 132;                  // words
constexpr int kSb = kGhs + 24 * kGhsStride * 4;  // 185216  (96 f32 biases)
constexpr int kSmemBytes = 186368;               // 1 CTA/SM (2x > 228KB)
}  // namespace

// Device-global scratch (no allocation allowed).
__device__ __align__(16) __half g_h[2][2][kB][kH];  // [dir][buf][b][k], fp16
__device__ float g_ssum[2][kB];          // running spart accumulators
__device__ unsigned int g_hcnt4[2][4][32];  // per-chunk h counters (128B apart)
__device__ unsigned int g_scnt[2][32];      // aggregated spart counters
__device__ int g_mask_mode;                 // 0=u8, 1=i32, 2=f32

__device__ __forceinline__ float sigmoid_fast(float v) {
  return __fdividef(1.f, 1.f + __expf(-v));
}
__device__ __forceinline__ float tanh_fast(float v) {
  return 1.f - __fdividef(2.f, 1.f + __expf(2.f * v));
}
__device__ __forceinline__ uint32_t smem_u32(const void* p) {
  uint32_t a;
  asm("{ .reg .u64 t; cvta.to.shared.u64 t, %1; cvt.u32.u64 %0, t; }"
      : "=r"(a) : "l"(p));
  return a;
}
__device__ __forceinline__ void mma16816(float* d, uint32_t a0, uint32_t a1,
                                         uint32_t a2, uint32_t a3, uint32_t b0,
                                         uint32_t b1) {
  asm volatile(
      "mma.sync.aligned.m16n8k16.row.col.f32.f16.f16.f32 "
      "{%0,%1,%2,%3},{%4,%5,%6,%7},{%8,%9},{%0,%1,%2,%3};"
      : "+f"(d[0]), "+f"(d[1]), "+f"(d[2]), "+f"(d[3])
      : "r"(a0), "r"(a1), "r"(a2), "r"(a3), "r"(b0), "r"(b1));
}
#define LDM4(r, addr)                                                  \
  asm volatile(                                                        \
      "ldmatrix.sync.aligned.m8n8.x4.shared.b16 {%0,%1,%2,%3}, [%4];"  \
      : "=r"((r)[0]), "=r"((r)[1]), "=r"((r)[2]), "=r"((r)[3])         \
      : "r"(addr))

__device__ __forceinline__ void bar_sync(int id, int cnt) {
  asm volatile("bar.sync %0, %1;" ::"r"(id), "r"(cnt) : "memory");
}
__device__ __forceinline__ void bar_arrive(int id, int cnt) {
  asm volatile("bar.arrive %0, %1;" ::"r"(id), "r"(cnt) : "memory");
}
__device__ __forceinline__ unsigned int poll_ge(const unsigned int* fp,
                                                unsigned int need) {
  unsigned int v;
  do {
    asm volatile("ld.acquire.gpu.u32 %0, [%1];" : "=r"(v) : "l"(fp) : "memory");
  } while ((int)(v - need) < 0);
  return v;
}
__device__ __forceinline__ void cnt_bump(unsigned int* cp) {
  asm volatile("fence.acq_rel.gpu;" ::: "memory");
  asm volatile("red.release.gpu.global.add.u32 [%0], 1;" ::"l"(cp) : "memory");
}
__device__ __forceinline__ void red_add_f32(float* p, float v) {
  asm volatile("red.release.gpu.global.add.f32 [%0], %1;" ::"l"(p), "f"(v)
               : "memory");
}

__global__ void init_kernel(const void* __restrict__ mask) {
  int idx = blockIdx.x * blockDim.x + threadIdx.x;  // 65536 threads
  if (idx < 32768)  // g_h = 2*2*128*512 halfs = 512KB = 32768 uint4
    reinterpret_cast<uint4*>(&g_h[0][0][0][0])[idx] = make_uint4(0, 0, 0, 0);
  if (idx < 256) {
    (&g_hcnt4[0][0][0])[idx] = 0u;
    (&g_ssum[0][0])[idx] = 0.f;
  }
  if (idx < 64) (&g_scnt[0][0])[idx] = 0u;
  if (idx == 0) {
    const int* i32 = (const int*)mask;
    const float* f32 = (const float*)mask;
    bool is_i32 = true, is_f32 = true;
    for (int i = 0; i < 64; ++i) {
      int v = i32[i];
      if (v != 0 && v != 1) is_i32 = false;
      float f = f32[i];
      if (!(f == 0.f || f == 1.f)) is_f32 = false;
    }
    g_mask_mode = is_i32 ? 1 : (is_f32 ? 2 : 0);
  }
}

__global__ void __launch_bounds__(kThreads, 1)
bidgru_kernel(const float* __restrict__ x, const void* __restrict__ mask,
              const float* __restrict__ wf_ih, const float* __restrict__ wf_hh,
              const float* __restrict__ bf_ih, const float* __restrict__ bf_hh,
              const float* __restrict__ wb_ih, const float* __restrict__ wb_hh,
              const float* __restrict__ bb_ih, const float* __restrict__ bb_hh,
              const float* __restrict__ p_w1, const float* __restrict__ p_b1,
              const float* __restrict__ p_w2, const float* __restrict__ p_b2,
              float* __restrict__ out) {
  extern __shared__ __align__(16) char smem_c[];
  const uint32_t smem_base = smem_u32(smem_c);
  float* sb = reinterpret_cast<float*>(smem_c + kSb);
  float* ghs = reinterpret_cast<float*>(smem_c + kGhs);

  const int tid = threadIdx.x;
  const int wid = tid >> 5;
  const int lane = tid & 31;
  const int d = blockIdx.x >> 6;
  const int c = blockIdx.x & 63;
  const int j0 = c * 8;

  const float* w_hh = d ? wb_hh : wf_hh;
  const float* w_ih = d ? wb_ih : wf_ih;
  const float* b_hh = d ? bb_hh : bf_hh;
  const float* b_ih = d ? bb_ih : bf_ih;
  const int mmode = g_mask_mode;

  // ---- one-time W staging: fp32 -> fp16, rows [n][k] stride 520 ----
  for (int i = tid; i < 32 * kH; i += kThreads) {
    int r = i >> 9, k = i & (kH - 1);
    float v = (r < 24) ? w_hh[((r >> 3) * kH + j0 + (r & 7)) * kH + k]
                       : p_w1[(j0 + (r & 7)) * kH + k];
    reinterpret_cast<__half*>(smem_c)[r * kWStride + k] = __float2half_rn(v);
  }
  if (tid < 24) {
    int g = tid >> 3, jj = tid & 7;
    sb[tid] = b_hh[g * kH + j0 + jj];
    sb[24 + tid] = b_ih[g * kH + j0 + jj];
    sb[48 + tid] = w_ih[g * kH + j0 + jj];
  } else if (tid < 32) {
    int jj = tid - 24;
    sb[72 + jj] = p_b1[j0 + jj];
    sb[80 + jj] = p_w2[j0 + jj];
  } else if (tid == 32) {
    sb[88] = p_b2[0];
  }
  __syncthreads();

  const bool is_mma = tid < 128;
  const int r0q = lane >> 2, cq = lane & 3;
  const int md = lane >> 3, mr = lane & 7;
  const uint32_t a_off = (uint32_t)(((md & 1) * 8 + mr) * kARow + (md >> 1) * 16);
  const uint32_t b_off =
      (uint32_t)((((md >> 1) * 8 + mr) * kWStride) * 2 + (md & 1) * 16);
  const uint32_t w_addr = smem_base;

  // staging/epilogue geometry (tid in [128,384))
  const int t1 = tid - 128;  // 0..255
  const int grp = t1 >> 7;   // group 0: chunks 0,2 ; group 1: chunks 1,3
  const int s = t1 & 127;
  const int q16 = s & 15, br0 = s >> 4;
  const int eb = t1 >> 1, ehalf = t1 & 1;
  float hreg[4] = {0.f, 0.f, 0.f, 0.f};
  float sprev = 0.f;  // running spart sum seen so far

  unsigned int* scnt = &g_scnt[d][0];

  int cur = 0;

  for (int t = 0; t < kT; ++t) {
    const int pos = d ? (kT - 1 - t) : t;
    const int nxt = cur ^ 1;

    if (is_mma) {
      // ================= MMA warps (0-3) =================
      float acc[2][4][4];
#pragma unroll
      for (int mt = 0; mt < 2; ++mt)
#pragma unroll
        for (int nt = 0; nt < 4; ++nt)
#pragma unroll
          for (int q = 0; q < 4; ++q) acc[mt][nt][q] = 0.f;

#pragma unroll
      for (int kc = 0; kc < 4; ++kc) {
        bar_sync(1 + kc, 256);  // chunk kc staged
        const uint32_t ab = smem_base + kABase + kc * kAPart;
        const uint32_t bko = (uint32_t)(kc * 256);

        if (kc < 3) {
#pragma unroll
          for (int ks = 0; ks < 8; ++ks) {
            uint32_t ah[2][4];
#pragma unroll
            for (int mt = 0; mt < 2; ++mt)
              LDM4(ah[mt],
                   ab + a_off + (uint32_t)((2 * wid + mt) * 16 * kARow + ks * 32));
#pragma unroll
            for (int np = 0; np < 2; ++np) {
              uint32_t bv[4];
              LDM4(bv, w_addr + b_off + (uint32_t)(np * 16 * kWStride * 2) + bko +
                           (uint32_t)(ks * 32));
#pragma unroll
              for (int nti = 0; nti < 2; ++nti) {
                const int nt = np * 2 + nti;
#pragma unroll
                for (int mt = 0; mt < 2; ++mt)
                  mma16816(acc[mt][nt], ah[mt][0], ah[mt][1], ah[mt][2],
                           ah[mt][3], bv[nti * 2], bv[nti * 2 + 1]);
              }
            }
          }
        } else {
          // pass 1: np=1 (n-tiles 2,3 incl. predictor rows)
#pragma unroll
          for (int ks = 0; ks < 8; ++ks) {
            uint32_t ah[2][4];
#pragma unroll
            for (int mt = 0; mt < 2; ++mt)
              LDM4(ah[mt],
                   ab + a_off + (uint32_t)((2 * wid + mt) * 16 * kARow + ks * 32));
            uint32_t bv[4];
            LDM4(bv, w_addr + b_off + (uint32_t)(16 * kWStride * 2) + bko +
                         (uint32_t)(ks * 32));
#pragma unroll
            for (int nti = 0; nti < 2; ++nti) {
              const int nt = 2 + nti;
#pragma unroll
              for (int mt = 0; mt < 2; ++mt)
                mma16816(acc[mt][nt], ah[mt][0], ah[mt][1], ah[mt][2], ah[mt][3],
                         bv[nti * 2], bv[nti * 2 + 1]);
            }
          }
          {  // spart via running-sum red.add (overlaps with pass 2)
            const float b1a = sb[72 + 2 * cq], b1b = sb[72 + 2 * cq + 1];
            const float w2a = sb[80 + 2 * cq], w2b = sb[80 + 2 * cq + 1];
#pragma unroll
            for (int mt = 0; mt < 2; ++mt) {
              float glo = fmaxf(acc[mt][3][0] + b1a, 0.f) * w2a +
                          fmaxf(acc[mt][3][1] + b1b, 0.f) * w2b;
              float ghi = fmaxf(acc[mt][3][2] + b1a, 0.f) * w2a +
                          fmaxf(acc[mt][3][3] + b1b, 0.f) * w2b;
              glo += __shfl_xor_sync(0xFFFFFFFFu, glo, 1);
              glo += __shfl_xor_sync(0xFFFFFFFFu, glo, 2);
              ghi += __shfl_xor_sync(0xFFFFFFFFu, ghi, 1);
              ghi += __shfl_xor_sync(0xFFFFFFFFu, ghi, 2);
              if (cq == 0) {
                const int br = (2 * wid + mt) * 16 + r0q;
                red_add_f32(&g_ssum[d][br], glo);
                red_add_f32(&g_ssum[d][br + 8], ghi);
              }
            }
            bar_sync(6, 128);
            if (tid == 0) cnt_bump(scnt);
          }
          // pass 2: np=0 (gate n-tiles 0,1)
#pragma unroll
          for (int ks = 0; ks < 8; ++ks) {
            uint32_t ah[2][4];
#pragma unroll
            for (int mt = 0; mt < 2; ++mt)
              LDM4(ah[mt],
                   ab + a_off + (uint32_t)((2 * wid + mt) * 16 * kARow + ks * 32));
            uint32_t bv[4];
            LDM4(bv, w_addr + b_off + bko + (uint32_t)(ks * 32));
#pragma unroll
            for (int nti = 0; nti < 2; ++nti) {
#pragma unroll
              for (int mt = 0; mt < 2; ++mt)
                mma16816(acc[mt][nti], ah[mt][0], ah[mt][1], ah[mt][2], ah[mt][3],
                         bv[nti * 2], bv[nti * 2 + 1]);
            }
          }
        }
      }

      // scatter gate rows (n 0..23) to ghs, then signal epilogue
#pragma unroll
      for (int mt = 0; mt < 2; ++mt) {
        const int br = (2 * wid + mt) * 16 + r0q;
#pragma unroll
        for (int nt = 0; nt < 3; ++nt) {
          const int n0 = nt * 8 + cq * 2;
          ghs[n0 * kGhsStride + br] = acc[mt][nt][0];
          ghs[(n0 + 1) * kGhsStride + br] = acc[mt][nt][1];
          ghs[n0 * kGhsStride + br + 8] = acc[mt][nt][2];
          ghs[(n0 + 1) * kGhsStride + br + 8] = acc[mt][nt][3];
        }
      }
      bar_arrive(7, 384);
    } else {
      // ================= staging + epilogue warps (4-11) =================
      // prefetch x/mask early (independent of all sync)
      float xv = __ldg(&x[(size_t)eb * kT + pos]);
      bool m;
      {
        const size_t midx = (size_t)eb * kT + pos;
        if (mmode == 1)
          m = ((const int*)mask)[midx] != 0;
        else if (mmode == 2)
          m = ((const float*)mask)[midx] != 0.f;
        else
          m = ((const uint8_t*)mask)[midx] != 0;
      }

      const uint4* hb4 = reinterpret_cast<const uint4*>(&g_h[d][cur][0][0]);
#pragma unroll
      for (int kk = 0; kk < 2; ++kk) {
        const int kc = grp + 2 * kk;
        // gate: the 16 producer CTAs of chunk kc published h_{t-1}
        if (t > 0) {
          if (s == 0) poll_ge(&g_hcnt4[d][kc][0], (unsigned)(16 * t));
          bar_sync(10 + grp, 128);
        }
#pragma unroll 4
        for (int i = 0; i < 16; ++i) {
          const int b = i * 8 + br0;
          uint4 v = __ldcg(hb4 + b * 64 + kc * 16 + q16);
          *reinterpret_cast<uint4*>(smem_c + kABase + kc * kAPart + b * kARow +
                                    q16 * 16) = v;
        }
        bar_arrive(1 + kc, 256);  // chunk staged
      }

      // ---- epilogue ----
      // gate: all CTAs added spart_t (counter == 64*(t+1))
      if (t1 == 0) poll_ge(scnt, (unsigned)(64 * (t + 1)));
      bar_sync(8, 256);

      const float stot = __ldcg(&g_ssum[d][eb]);
      const float scal = tanh_fast((stot - sprev) + sb[88]);
      sprev = stot;
      const float xin = m ? scal : xv;

      bar_sync(7, 384);  // ghs ready

      float onew[4];
      unsigned short h16[4];
      const int jbase = ehalf * 4;
#pragma unroll
      for (int u = 0; u < 4; ++u) {
        const int jj = jbase + u;
        float gr = ghs[jj * kGhsStride + eb] + sb[jj] +
                   fmaf(xin, sb[48 + jj], sb[24 + jj]);
        float gz = ghs[(8 + jj) * kGhsStride + eb] + sb[8 + jj] +
                   fmaf(xin, sb[48 + 8 + jj], sb[24 + 8 + jj]);
        float ghn = ghs[(16 + jj) * kGhsStride + eb] + sb[16 + jj];
        float gin = fmaf(xin, sb[48 + 16 + jj], sb[24 + 16 + jj]);
        float r = sigmoid_fast(gr);
        float z = sigmoid_fast(gz);
        float n = tanh_fast(fmaf(r, ghn, gin));
        float hnew = fmaf(z, hreg[u] - n, n);
        hreg[u] = hnew;
        onew[u] = hnew;
        h16[u] = __half_as_ushort(__float2half_rn(hnew));
      }
      uint2 vh;
      vh.x = (uint32_t)h16[0] | ((uint32_t)h16[1] << 16);
      vh.y = (uint32_t)h16[2] | ((uint32_t)h16[3] << 16);
      __stcg(reinterpret_cast<uint2*>(&g_h[d][nxt][eb][j0 + jbase]), vh);

      bar_sync(9, 256);  // all h' stores issued
      if (t1 == 0) cnt_bump(&g_hcnt4[d][c >> 4][0]);

      float* op =
          out + ((size_t)eb << 20) + ((size_t)pos << 10) + (d << 9) + j0 + jbase;
      *reinterpret_cast<float4*>(op) =
          make_float4(onew[0], onew[1], onew[2], onew[3]);
    }
    cur = nxt;
  }
}

extern "C" void kernel_launch(void* const* d_in, const int* in_sizes, int n_in,
                              void* d_out, int out_size) {
  const float* x = (const float*)d_in[0];
  const void* mask = (const void*)d_in[1];
  const float* wf_ih = (const float*)d_in[2];
  const float* wf_hh = (const float*)d_in[3];
  const float* bf_ih = (const float*)d_in[4];
  const float* bf_hh = (const float*)d_in[5];
  const float* wb_ih = (const float*)d_in[6];
  const float* wb_hh = (const float*)d_in[7];
  const float* bb_ih = (const float*)d_in[8];
  const float* bb_hh = (const float*)d_in[9];
  const float* p_w1 = (const float*)d_in[10];
  const float* p_b1 = (const float*)d_in[11];
  const float* p_w2 = (const float*)d_in[12];
  const float* p_b2 = (const float*)d_in[13];
  float* out = (float*)d_out;

  (void)in_sizes;
  (void)n_in;
  (void)out_size;

  cudaFuncSetAttribute(bidgru_kernel, cudaFuncAttributeMaxDynamicSharedMemorySize,
                       kSmemBytes);
  init_kernel<<<256, 256>>>(mask);
  bidgru_kernel<<<kNCta, kThreads, kSmemBytes>>>(x, mask, wf_ih, wf_hh, bf_ih,
                                                 bf_hh, wb_ih, wb_hh, bb_ih, bb_hh,
                                                 p_w1, p_b1, p_w2, p_b2, out);
}

// round 12
// speedup vs baseline: 1.8871x; 1.8871x over previous
#include <cuda_runtime.h>
#include <cuda_fp16.h>
#include <stdint.h>

// ---------------------------------------------------------------------------
// Bidirectional GRU w/ predictor feedback. B=128, T=1024, H=512.
// R12 re-partition: 2 dirs x 4 groups x 16 CTAs. Group g owns batches
// [32g,32g+32); CTA c of a group owns hidden columns [32c,32c+32).
// Per CTA/step: C[32b x 128n] = h_g[32x512] @ Wc[128x512]^T (mma m16n8k16
// fp16). W rows 0..95 = gates (r,z,n x 32 cols), 96..127 = p_w1 rows.
// Warps 0-2: gate n-tiles; warp 3: predictor n-tiles only (publishes spart
// from accumulators with a warp-local bar). Warps 4-11: stage A (one shot,
// 32KB) + epilogue. Cross-CTA rendezvous is 16-wide (per-group counters).
// ---------------------------------------------------------------------------

namespace {
constexpr int kT = 1024;
constexpr int kThreads = 384;
constexpr int kRowB = 1040;  // bytes per 512-fp16 row (+16B pad): 260w = 4 mod 32

// SMEM layout (bytes)
constexpr int kW = 0;                      // 128 rows x 1040 = 133120
constexpr int kA = 133120;                 // 32 rows x 1040  = 33280
constexpr int kGhs = 166400;               // [96][37] f32    = 14208
constexpr int kGhsW = 37;                  // words; conflict-free both sides
constexpr int kSb = 180608;                // 384 f32 biases
constexpr int kSmemBytes = 184320;         // > 114KB -> 1 CTA/SM
}  // namespace

// Device-global scratch (no allocation allowed).
__device__ __align__(16) __half g_h[2][2][128][512];  // [dir][buf][b][k]
__device__ float g_spart[2][4][32][16];               // [dir][grp][b][cta]
__device__ unsigned int g_hcnt[2][4][32];             // per-group h counters
__device__ unsigned int g_scnt[2][4][32];             // per-group spart counters
__device__ int g_mask_mode;                           // 0=u8, 1=i32, 2=f32

__device__ __forceinline__ float sigmoid_fast(float v) {
  return __fdividef(1.f, 1.f + __expf(-v));
}
__device__ __forceinline__ float tanh_fast(float v) {
  return 1.f - __fdividef(2.f, 1.f + __expf(2.f * v));
}
__device__ __forceinline__ uint32_t smem_u32(const void* p) {
  uint32_t a;
  asm("{ .reg .u64 t; cvta.to.shared.u64 t, %1; cvt.u32.u64 %0, t; }"
      : "=r"(a) : "l"(p));
  return a;
}
__device__ __forceinline__ void mma16816(float* d, uint32_t a0, uint32_t a1,
                                         uint32_t a2, uint32_t a3, uint32_t b0,
                                         uint32_t b1) {
  asm volatile(
      "mma.sync.aligned.m16n8k16.row.col.f32.f16.f16.f32 "
      "{%0,%1,%2,%3},{%4,%5,%6,%7},{%8,%9},{%0,%1,%2,%3};"
      : "+f"(d[0]), "+f"(d[1]), "+f"(d[2]), "+f"(d[3])
      : "r"(a0), "r"(a1), "r"(a2), "r"(a3), "r"(b0), "r"(b1));
}
#define LDM4(r, addr)                                                  \
  asm volatile(                                                        \
      "ldmatrix.sync.aligned.m8n8.x4.shared.b16 {%0,%1,%2,%3}, [%4];"  \
      : "=r"((r)[0]), "=r"((r)[1]), "=r"((r)[2]), "=r"((r)[3])         \
      : "r"(addr))

__device__ __forceinline__ void bar_sync(int id, int cnt) {
  asm volatile("bar.sync %0, %1;" ::"r"(id), "r"(cnt) : "memory");
}
__device__ __forceinline__ void bar_arrive(int id, int cnt) {
  asm volatile("bar.arrive %0, %1;" ::"r"(id), "r"(cnt) : "memory");
}
__device__ __forceinline__ unsigned int poll_ge(const unsigned int* fp,
                                                unsigned int need) {
  unsigned int v;
  do {
    asm volatile("ld.acquire.gpu.u32 %0, [%1];" : "=r"(v) : "l"(fp) : "memory");
  } while ((int)(v - need) < 0);
  return v;
}
__device__ __forceinline__ void cnt_bump(unsigned int* cp) {
  asm volatile("fence.acq_rel.gpu;" ::: "memory");
  asm volatile("red.release.gpu.global.add.u32 [%0], 1;" ::"l"(cp) : "memory");
}

__global__ void init_kernel(const void* __restrict__ mask) {
  int idx = blockIdx.x * blockDim.x + threadIdx.x;  // 65536 threads
  if (idx < 32768)  // g_h = 512KB = 32768 uint4
    reinterpret_cast<uint4*>(&g_h[0][0][0][0])[idx] = make_uint4(0, 0, 0, 0);
  if (idx < 256) {
    (&g_hcnt[0][0][0])[idx] = 0u;
    (&g_scnt[0][0][0])[idx] = 0u;
  }
  if (idx == 0) {
    const int* i32 = (const int*)mask;
    const float* f32 = (const float*)mask;
    bool is_i32 = true, is_f32 = true;
    for (int i = 0; i < 64; ++i) {
      int v = i32[i];
      if (v != 0 && v != 1) is_i32 = false;
      float f = f32[i];
      if (!(f == 0.f || f == 1.f)) is_f32 = false;
    }
    g_mask_mode = is_i32 ? 1 : (is_f32 ? 2 : 0);
  }
}

__global__ void __launch_bounds__(kThreads, 1)
bidgru_kernel(const float* __restrict__ x, const void* __restrict__ mask,
              const float* __restrict__ wf_ih, const float* __restrict__ wf_hh,
              const float* __restrict__ bf_ih, const float* __restrict__ bf_hh,
              const float* __restrict__ wb_ih, const float* __restrict__ wb_hh,
              const float* __restrict__ bb_ih, const float* __restrict__ bb_hh,
              const float* __restrict__ p_w1, const float* __restrict__ p_b1,
              const float* __restrict__ p_w2, const float* __restrict__ p_b2,
              float* __restrict__ out) {
  extern __shared__ __align__(16) char smem_c[];
  const uint32_t smem_base = smem_u32(smem_c);
  float* sb = reinterpret_cast<float*>(smem_c + kSb);
  float* ghs = reinterpret_cast<float*>(smem_c + kGhs);

  const int tid = threadIdx.x;
  const int wid = tid >> 5;
  const int lane = tid & 31;
  const int d = blockIdx.x >> 6;          // direction
  const int g = (blockIdx.x >> 4) & 3;    // batch group
  const int c = blockIdx.x & 15;          // column CTA within group
  const int j0c = c * 32;                 // base hidden column
  const int b0g = g * 32;                 // base batch

  const float* w_hh = d ? wb_hh : wf_hh;
  const float* w_ih = d ? wb_ih : wf_ih;
  const float* b_hh = d ? bb_hh : bf_hh;
  const float* b_ih = d ? bb_ih : bf_ih;
  const int mmode = g_mask_mode;

  // ---- one-time W staging: fp32 -> fp16, 128 rows x 512 k, stride 1040B ----
  // rows 0..95: w_hh rows gate*512 + j0c + (r&31); rows 96..127: p_w1.
  for (int i = tid; i < 128 * 512; i += kThreads) {
    int r = i >> 9, k = i & 511;
    float v = (r < 96) ? w_hh[((r >> 5) * 512 + j0c + (r & 31)) * 512 + k]
                       : p_w1[(j0c + (r - 96)) * 512 + k];
    *reinterpret_cast<__half*>(smem_c + kW + r * kRowB + k * 2) =
        __float2half_rn(v);
  }
  if (tid < 96) {
    int gt = tid >> 5, jc = tid & 31;
    sb[tid] = b_hh[gt * 512 + j0c + jc];
    sb[96 + tid] = b_ih[gt * 512 + j0c + jc];
    sb[192 + tid] = w_ih[gt * 512 + j0c + jc];
  } else if (tid < 128) {
    int jc = tid - 96;
    sb[288 + jc] = p_b1[j0c + jc];
    sb[320 + jc] = p_w2[j0c + jc];
  } else if (tid == 128) {
    sb[352] = p_b2[0];
  }
  __syncthreads();

  const bool is_mma = tid < 128;
  const int r0q = lane >> 2, cq = lane & 3;
  const int md = lane >> 3, mr = lane & 7;
  const uint32_t a_off =
      (uint32_t)(((md & 1) * 8 + mr) * kRowB + (md >> 1) * 16);
  const uint32_t b_off =
      (uint32_t)(((md >> 1) * 8 + mr) * kRowB + (md & 1) * 16);

  // staging/epilogue geometry (tid in [128,384))
  const int t1 = tid - 128;              // 0..255
  const int sw = t1 >> 5;                // staging warp index 0..7
  const int eb = t1 >> 3;                // local batch 0..31
  const int jq = t1 & 7;                 // column quad 0..7 -> j = jq*4
  const int b_glob = b0g + eb;
  float hreg[4] = {0.f, 0.f, 0.f, 0.f};

  unsigned int* hcnt = &g_hcnt[d][g][0];
  unsigned int* scnt = &g_scnt[d][g][0];

  int cur = 0;

  for (int t = 0; t < kT; ++t) {
    const int pos = d ? (kT - 1 - t) : t;
    const int nxt = cur ^ 1;

    if (is_mma) {
      // ================= MMA warps 0-3 =================
      bar_sync(1, 384);  // A staged
      float acc[2][4][4];
#pragma unroll
      for (int mt = 0; mt < 2; ++mt)
#pragma unroll
        for (int nt = 0; nt < 4; ++nt)
#pragma unroll
          for (int q = 0; q < 4; ++q) acc[mt][nt][q] = 0.f;

      const uint32_t ab = smem_base + kA;
      const uint32_t wb = smem_base + kW + (uint32_t)(wid * 32 * kRowB);
#pragma unroll 4
      for (int kg = 0; kg < 32; ++kg) {
        uint32_t ah[2][4];
#pragma unroll
        for (int mt = 0; mt < 2; ++mt)
          LDM4(ah[mt], ab + a_off + (uint32_t)(mt * 16 * kRowB + kg * 32));
#pragma unroll
        for (int p = 0; p < 2; ++p) {
          uint32_t bv[4];
          LDM4(bv, wb + b_off + (uint32_t)(p * 16 * kRowB + kg * 32));
#pragma unroll
          for (int i = 0; i < 2; ++i) {
            const int nt = p * 2 + i;
#pragma unroll
            for (int mt = 0; mt < 2; ++mt)
              mma16816(acc[mt][nt], ah[mt][0], ah[mt][1], ah[mt][2], ah[mt][3],
                       bv[2 * i], bv[2 * i + 1]);
          }
        }
      }

      if (wid < 3) {
        // scatter 4 gate n-tiles to ghs (conflict-free, stride 37)
#pragma unroll
        for (int mt = 0; mt < 2; ++mt) {
          const int br = mt * 16 + r0q;
#pragma unroll
          for (int nt = 0; nt < 4; ++nt) {
            const int n0 = (4 * wid + nt) * 8 + cq * 2;
            ghs[n0 * kGhsW + br] = acc[mt][nt][0];
            ghs[(n0 + 1) * kGhsW + br] = acc[mt][nt][1];
            ghs[n0 * kGhsW + br + 8] = acc[mt][nt][2];
            ghs[(n0 + 1) * kGhsW + br + 8] = acc[mt][nt][3];
          }
        }
      } else {
        // warp 3: predictor rows only -> spart straight from accumulators
#pragma unroll
        for (int mt = 0; mt < 2; ++mt) {
          float glo = 0.f, ghi = 0.f;
#pragma unroll
          for (int nt = 0; nt < 4; ++nt) {
            const int pr = nt * 8 + 2 * cq;
            const float b1a = sb[288 + pr], b1b = sb[288 + pr + 1];
            const float w2a = sb[320 + pr], w2b = sb[320 + pr + 1];
            glo += fmaxf(acc[mt][nt][0] + b1a, 0.f) * w2a +
                   fmaxf(acc[mt][nt][1] + b1b, 0.f) * w2b;
            ghi += fmaxf(acc[mt][nt][2] + b1a, 0.f) * w2a +
                   fmaxf(acc[mt][nt][3] + b1b, 0.f) * w2b;
          }
          glo += __shfl_xor_sync(0xFFFFFFFFu, glo, 1);
          glo += __shfl_xor_sync(0xFFFFFFFFu, glo, 2);
          ghi += __shfl_xor_sync(0xFFFFFFFFu, ghi, 1);
          ghi += __shfl_xor_sync(0xFFFFFFFFu, ghi, 2);
          if (cq == 0) {
            const int b = mt * 16 + r0q;
            __stcg(&g_spart[d][g][b][c], glo);
            __stcg(&g_spart[d][g][b + 8][c], ghi);
          }
        }
        bar_sync(6, 32);  // warp-local: drain spart stores
        if (lane == 0) cnt_bump(scnt);
      }
      bar_arrive(7, 384);  // ghs ready
    } else {
      // ================= staging + epilogue (warps 4-11) =================
      if (t > 0) {
        if (tid == 128) poll_ge(hcnt, (unsigned)(16 * t));
        bar_sync(5, 256);
      }
      // stage A: 32 rows x 1024B, warp sw handles tasks sw, 8+sw, ...
      {
        const uint4* hb4 = reinterpret_cast<const uint4*>(&g_h[d][cur][0][0]);
#pragma unroll
        for (int it = 0; it < 8; ++it) {
          const int task = it * 8 + sw;       // 0..63
          const int b = task >> 1;            // local batch row
          const int k16 = (task & 1) * 32 + lane;
          uint4 v = __ldcg(hb4 + (b0g + b) * 64 + k16);
          *reinterpret_cast<uint4*>(smem_c + kA + b * kRowB + k16 * 16) = v;
        }
      }
      bar_arrive(1, 384);

      // prefetch x/mask (overlaps MMA)
      float xv = __ldg(&x[(size_t)b_glob * kT + pos]);
      bool m;
      {
        const size_t midx = (size_t)b_glob * kT + pos;
        if (mmode == 1)
          m = ((const int*)mask)[midx] != 0;
        else if (mmode == 2)
          m = ((const float*)mask)[midx] != 0.f;
        else
          m = ((const uint8_t*)mask)[midx] != 0;
      }

      // spart: wait for the 16 group CTAs, gather one 64B row
      if (tid == 128) poll_ge(scnt, (unsigned)(16 * (t + 1)));
      bar_sync(8, 256);
      float a = 0.f;
      {
        const float4* pp =
            reinterpret_cast<const float4*>(&g_spart[d][g][eb][0]);
#pragma unroll
        for (int q = 0; q < 4; ++q) {
          float4 v = __ldcg(pp + q);
          a += v.x + v.y + v.z + v.w;
        }
      }
      const float scal = tanh_fast(a + sb[352]);
      const float xin = m ? scal : xv;

      bar_sync(7, 384);  // ghs ready

      float onew[4];
      unsigned short h16[4];
      const int j4 = jq * 4;
#pragma unroll
      for (int u = 0; u < 4; ++u) {
        const int j = j4 + u;
        float gr =
            ghs[j * kGhsW + eb] + sb[j] + fmaf(xin, sb[192 + j], sb[96 + j]);
        float gz = ghs[(32 + j) * kGhsW + eb] + sb[32 + j] +
                   fmaf(xin, sb[192 + 32 + j], sb[96 + 32 + j]);
        float ghn = ghs[(64 + j) * kGhsW + eb] + sb[64 + j];
        float gin = fmaf(xin, sb[192 + 64 + j], sb[96 + 64 + j]);
        float r = sigmoid_fast(gr);
        float z = sigmoid_fast(gz);
        float n = tanh_fast(fmaf(r, ghn, gin));
        float hnew = fmaf(z, hreg[u] - n, n);
        hreg[u] = hnew;
        onew[u] = hnew;
        h16[u] = __half_as_ushort(__float2half_rn(hnew));
      }
      uint2 vh;
      vh.x = (uint32_t)h16[0] | ((uint32_t)h16[1] << 16);
      vh.y = (uint32_t)h16[2] | ((uint32_t)h16[3] << 16);
      __stcg(reinterpret_cast<uint2*>(&g_h[d][nxt][b_glob][j0c + j4]), vh);

      bar_sync(9, 256);  // all h' stores done
      if (tid == 128) cnt_bump(hcnt);

      float* op = out + ((size_t)b_glob << 20) + ((size_t)pos << 10) +
                  (d << 9) + j0c + j4;
      *reinterpret_cast<float4*>(op) =
          make_float4(onew[0], onew[1], onew[2], onew[3]);
    }
    cur = nxt;
  }
}

extern "C" void kernel_launch(void* const* d_in, const int* in_sizes, int n_in,
                              void* d_out, int out_size) {
  const float* x = (const float*)d_in[0];
  const void* mask = (const void*)d_in[1];
  const float* wf_ih = (const float*)d_in[2];
  const float* wf_hh = (const float*)d_in[3];
  const float* bf_ih = (const float*)d_in[4];
  const float* bf_hh = (const float*)d_in[5];
  const float* wb_ih = (const float*)d_in[6];
  const float* wb_hh = (const float*)d_in[7];
  const float* bb_ih = (const float*)d_in[8];
  const float* bb_hh = (const float*)d_in[9];
  const float* p_w1 = (const float*)d_in[10];
  const float* p_b1 = (const float*)d_in[11];
  const float* p_w2 = (const float*)d_in[12];
  const float* p_b2 = (const float*)d_in[13];
  float* out = (float*)d_out;

  (void)in_sizes;
  (void)n_in;
  (void)out_size;

  cudaFuncSetAttribute(bidgru_kernel, cudaFuncAttributeMaxDynamicSharedMemorySize,
                       kSmemBytes);
  init_kernel<<<256, 256>>>(mask);
  bidgru_kernel<<<128, kThreads, kSmemBytes>>>(x, mask, wf_ih, wf_hh, bf_ih,
                                               bf_hh, wb_ih, wb_hh, bb_ih, bb_hh,
                                               p_w1, p_b1, p_w2, p_b2, out);
}

// round 13
// speedup vs baseline: 1.9062x; 1.0101x over previous
#include <cuda_runtime.h>
#include <cuda_fp16.h>
#include <stdint.h>

// ---------------------------------------------------------------------------
// Bidirectional GRU w/ predictor feedback. B=128, T=1024, H=512.
// 2 dirs x 4 groups x 16 CTAs; group g owns batches [32g,32g+32), CTA c owns
// hidden cols [32c,32c+32). C[32b x 128n] = h_g[32x512] @ Wc[128x512]^T via
// mma m16n8k16 fp16.
// R13: warp w (0-3) owns n-rows {8w(r), 32+8w(z), 64+8w(n), 96+8w(pred)} so
// gates are computed IN-REGISTER by the MMA warps (no ghs, no epilogue
// stage). Predictor n-tile is computed FIRST and spart published after ~1/4
// of the GEMM; its L2 round trip hides under the gate phase. Staging warps
// (4-11) stage A and warp 4 turns spart into sxin[32] in SMEM.
// ---------------------------------------------------------------------------

namespace {
constexpr int kT = 1024;
constexpr int kThreads = 384;
constexpr int kRowB = 1040;  // bytes per 512-fp16 row (+16B): 260w = 4 mod 32

// SMEM layout (bytes)
constexpr int kW = 0;              // 128 x 1040 = 133120
constexpr int kA = 133120;         // 32 x 1040  = 33280   (ends 166400)
constexpr int kSpp = 166400;       // 4 x 33 f32 = 528     (ends 166928)
constexpr int kSxin = 166928;      // 32 f32     = 128     (ends 167056)
constexpr int kSb = 167072;        // 384 f32    = 1536    (ends 168608)
constexpr int kSmemBytes = 169984; // > 114KB -> 1 CTA/SM
}  // namespace

// Device-global scratch (no allocation allowed).
__device__ __align__(16) __half g_h[2][2][128][512];  // [dir][buf][b][k]
__device__ float g_spart[2][4][32][16];               // [dir][grp][b][cta]
__device__ unsigned int g_hcnt[2][4][32];             // per-group h counters
__device__ unsigned int g_scnt[2][4][32];             // per-group spart cnts
__device__ int g_mask_mode;                           // 0=u8, 1=i32, 2=f32

__device__ __forceinline__ float sigmoid_fast(float v) {
  return __fdividef(1.f, 1.f + __expf(-v));
}
__device__ __forceinline__ float tanh_fast(float v) {
  return 1.f - __fdividef(2.f, 1.f + __expf(2.f * v));
}
__device__ __forceinline__ uint32_t smem_u32(const void* p) {
  uint32_t a;
  asm("{ .reg .u64 t; cvta.to.shared.u64 t, %1; cvt.u32.u64 %0, t; }"
      : "=r"(a) : "l"(p));
  return a;
}
__device__ __forceinline__ void mma16816(float* d, uint32_t a0, uint32_t a1,
                                         uint32_t a2, uint32_t a3, uint32_t b0,
                                         uint32_t b1) {
  asm volatile(
      "mma.sync.aligned.m16n8k16.row.col.f32.f16.f16.f32 "
      "{%0,%1,%2,%3},{%4,%5,%6,%7},{%8,%9},{%0,%1,%2,%3};"
      : "+f"(d[0]), "+f"(d[1]), "+f"(d[2]), "+f"(d[3])
      : "r"(a0), "r"(a1), "r"(a2), "r"(a3), "r"(b0), "r"(b1));
}
#define LDM4(r, addr)                                                  \
  asm volatile(                                                        \
      "ldmatrix.sync.aligned.m8n8.x4.shared.b16 {%0,%1,%2,%3}, [%4];"  \
      : "=r"((r)[0]), "=r"((r)[1]), "=r"((r)[2]), "=r"((r)[3])         \
      : "r"(addr))
#define LDM2(r, addr)                                             \
  asm volatile(                                                   \
      "ldmatrix.sync.aligned.m8n8.x2.shared.b16 {%0,%1}, [%2];"   \
      : "=r"((r)[0]), "=r"((r)[1])                                \
      : "r"(addr))

__device__ __forceinline__ void bar_sync(int id, int cnt) {
  asm volatile("bar.sync %0, %1;" ::"r"(id), "r"(cnt) : "memory");
}
__device__ __forceinline__ void bar_arrive(int id, int cnt) {
  asm volatile("bar.arrive %0, %1;" ::"r"(id), "r"(cnt) : "memory");
}
__device__ __forceinline__ unsigned int poll_ge(const unsigned int* fp,
                                                unsigned int need) {
  unsigned int v;
  do {
    asm volatile("ld.acquire.gpu.u32 %0, [%1];" : "=r"(v) : "l"(fp) : "memory");
  } while ((int)(v - need) < 0);
  return v;
}
__device__ __forceinline__ void cnt_bump(unsigned int* cp) {
  asm volatile("fence.acq_rel.gpu;" ::: "memory");
  asm volatile("red.release.gpu.global.add.u32 [%0], 1;" ::"l"(cp) : "memory");
}

__global__ void init_kernel(const void* __restrict__ mask) {
  int idx = blockIdx.x * blockDim.x + threadIdx.x;  // 65536 threads
  if (idx < 32768)  // g_h = 512KB = 32768 uint4
    reinterpret_cast<uint4*>(&g_h[0][0][0][0])[idx] = make_uint4(0, 0, 0, 0);
  if (idx < 256) {
    (&g_hcnt[0][0][0])[idx] = 0u;
    (&g_scnt[0][0][0])[idx] = 0u;
  }
  if (idx == 0) {
    const int* i32 = (const int*)mask;
    const float* f32 = (const float*)mask;
    bool is_i32 = true, is_f32 = true;
    for (int i = 0; i < 64; ++i) {
      int v = i32[i];
      if (v != 0 && v != 1) is_i32 = false;
      float f = f32[i];
      if (!(f == 0.f || f == 1.f)) is_f32 = false;
    }
    g_mask_mode = is_i32 ? 1 : (is_f32 ? 2 : 0);
  }
}

__global__ void __launch_bounds__(kThreads, 1)
bidgru_kernel(const float* __restrict__ x, const void* __restrict__ mask,
              const float* __restrict__ wf_ih, const float* __restrict__ wf_hh,
              const float* __restrict__ bf_ih, const float* __restrict__ bf_hh,
              const float* __restrict__ wb_ih, const float* __restrict__ wb_hh,
              const float* __restrict__ bb_ih, const float* __restrict__ bb_hh,
              const float* __restrict__ p_w1, const float* __restrict__ p_b1,
              const float* __restrict__ p_w2, const float* __restrict__ p_b2,
              float* __restrict__ out) {
  extern __shared__ __align__(16) char smem_c[];
  const uint32_t smem_base = smem_u32(smem_c);
  float* sb = reinterpret_cast<float*>(smem_c + kSb);
  float* spp = reinterpret_cast<float*>(smem_c + kSpp);
  float* sxin = reinterpret_cast<float*>(smem_c + kSxin);

  const int tid = threadIdx.x;
  const int wid = tid >> 5;
  const int lane = tid & 31;
  const int d = blockIdx.x >> 6;        // direction
  const int g = (blockIdx.x >> 4) & 3;  // batch group
  const int c = blockIdx.x & 15;        // column CTA within group
  const int j0c = c * 32;
  const int b0g = g * 32;

  const float* w_hh = d ? wb_hh : wf_hh;
  const float* w_ih = d ? wb_ih : wf_ih;
  const float* b_hh = d ? bb_hh : bf_hh;
  const float* b_ih = d ? bb_ih : bf_ih;
  const int mmode = g_mask_mode;

  // ---- one-time W staging: fp32 -> fp16, 128 rows x 512, stride 1040B ----
  // rows 0..95: w_hh rows (r>>5)*512 + j0c + (r&31); rows 96..127: p_w1.
  for (int i = tid; i < 128 * 512; i += kThreads) {
    int r = i >> 9, k = i & 511;
    float v = (r < 96) ? w_hh[((r >> 5) * 512 + j0c + (r & 31)) * 512 + k]
                       : p_w1[(j0c + (r - 96)) * 512 + k];
    *reinterpret_cast<__half*>(smem_c + kW + r * kRowB + k * 2) =
        __float2half_rn(v);
  }
  if (tid < 96) {
    int gt = tid >> 5, jc = tid & 31;
    sb[tid] = b_hh[gt * 512 + j0c + jc];
    sb[96 + tid] = b_ih[gt * 512 + j0c + jc];
    sb[192 + tid] = w_ih[gt * 512 + j0c + jc];
  } else if (tid < 128) {
    int jc = tid - 96;
    sb[288 + jc] = p_b1[j0c + jc];
    sb[320 + jc] = p_w2[j0c + jc];
  } else if (tid == 128) {
    sb[352] = p_b2[0];
  }
  __syncthreads();

  const bool is_mma = tid < 128;
  const int r0q = lane >> 2, cq = lane & 3;
  const int md = lane >> 3, mr = lane & 7;
  const uint32_t a_off =
      (uint32_t)(((md & 1) * 8 + mr) * kRowB + (md >> 1) * 16);
  const uint32_t b2_off =
      (uint32_t)((lane & 7) * kRowB + ((lane >> 3) & 1) * 16);

  // staging geometry (tid in [128,384))
  const int t1 = tid - 128;
  const int sw = t1 >> 5;  // staging warp 0..7

  // h state lives in MMA-warp registers: thread owns (b,j) pairs
  //   b = mt*16 + r0q + 8*half,  j = 8*wid + 2*cq + u
  float hreg[8];
#pragma unroll
  for (int u = 0; u < 8; ++u) hreg[u] = 0.f;

  unsigned int* hcnt = &g_hcnt[d][g][0];
  unsigned int* scnt = &g_scnt[d][g][0];

  int cur = 0;

  for (int t = 0; t < kT; ++t) {
    const int pos = d ? (kT - 1 - t) : t;
    const int nxt = cur ^ 1;

    if (is_mma) {
      // ================= MMA warps 0-3 =================
      bar_sync(1, 384);  // A staged
      const uint32_t ab = smem_base + kA;
      const uint32_t wR = smem_base + kW + (uint32_t)(8 * wid) * kRowB;
      const uint32_t wZ = wR + 32u * kRowB;
      const uint32_t wN = wR + 64u * kRowB;
      const uint32_t wP = wR + 96u * kRowB;

      float accR[2][4], accZ[2][4], accN[2][4], accP[2][4];
#pragma unroll
      for (int mt = 0; mt < 2; ++mt)
#pragma unroll
        for (int q = 0; q < 4; ++q) {
          accR[mt][q] = 0.f;
          accZ[mt][q] = 0.f;
          accN[mt][q] = 0.f;
          accP[mt][q] = 0.f;
        }

      // ---- phase 1: predictor n-tile only ----
#pragma unroll 4
      for (int kg = 0; kg < 32; ++kg) {
        uint32_t ah[2][4];
        LDM4(ah[0], ab + a_off + (uint32_t)(kg * 32));
        LDM4(ah[1], ab + a_off + 16u * kRowB + (uint32_t)(kg * 32));
        uint32_t bp[2];
        LDM2(bp, wP + b2_off + (uint32_t)(kg * 32));
#pragma unroll
        for (int mt = 0; mt < 2; ++mt)
          mma16816(accP[mt], ah[mt][0], ah[mt][1], ah[mt][2], ah[mt][3], bp[0],
                   bp[1]);
      }
      // spart partial for this warp's 8 pred cols
      {
        const int pr = 8 * wid + 2 * cq;
        const float b1a = sb[288 + pr], b1b = sb[288 + pr + 1];
        const float w2a = sb[320 + pr], w2b = sb[320 + pr + 1];
#pragma unroll
        for (int mt = 0; mt < 2; ++mt) {
          float glo = fmaxf(accP[mt][0] + b1a, 0.f) * w2a +
                      fmaxf(accP[mt][1] + b1b, 0.f) * w2b;
          float ghi = fmaxf(accP[mt][2] + b1a, 0.f) * w2a +
                      fmaxf(accP[mt][3] + b1b, 0.f) * w2b;
          glo += __shfl_xor_sync(0xFFFFFFFFu, glo, 1);
          glo += __shfl_xor_sync(0xFFFFFFFFu, glo, 2);
          ghi += __shfl_xor_sync(0xFFFFFFFFu, ghi, 1);
          ghi += __shfl_xor_sync(0xFFFFFFFFu, ghi, 2);
          if (cq == 0) {
            spp[wid * 33 + mt * 16 + r0q] = glo;
            spp[wid * 33 + mt * 16 + r0q + 8] = ghi;
          }
        }
      }
      bar_sync(6, 128);
      if (wid == 0) {  // combine + publish spart (round trip hides below)
        float v = spp[lane] + spp[33 + lane] + spp[66 + lane] + spp[99 + lane];
        __stcg(&g_spart[d][g][lane][c], v);
        __syncwarp();
        if (lane == 0) cnt_bump(scnt);
      }

      // ---- phase 2: gate n-tiles (r, z, n) ----
#pragma unroll 2
      for (int kg = 0; kg < 32; ++kg) {
        uint32_t ah[2][4];
        LDM4(ah[0], ab + a_off + (uint32_t)(kg * 32));
        LDM4(ah[1], ab + a_off + 16u * kRowB + (uint32_t)(kg * 32));
        uint32_t br2[2], bz2[2], bn2[2];
        LDM2(br2, wR + b2_off + (uint32_t)(kg * 32));
        LDM2(bz2, wZ + b2_off + (uint32_t)(kg * 32));
        LDM2(bn2, wN + b2_off + (uint32_t)(kg * 32));
#pragma unroll
        for (int mt = 0; mt < 2; ++mt) {
          mma16816(accR[mt], ah[mt][0], ah[mt][1], ah[mt][2], ah[mt][3], br2[0],
                   br2[1]);
          mma16816(accZ[mt], ah[mt][0], ah[mt][1], ah[mt][2], ah[mt][3], bz2[0],
                   bz2[1]);
          mma16816(accN[mt], ah[mt][0], ah[mt][1], ah[mt][2], ah[mt][3], bn2[0],
                   bn2[1]);
        }
      }

      bar_sync(11, 384);  // sxin ready (usually already open)

      // ---- gates + h update in-register ----
      const int j = 8 * wid + 2 * cq;
      const float sbr0 = sb[j], sbr1 = sb[j + 1];
      const float sbz0 = sb[32 + j], sbz1 = sb[32 + j + 1];
      const float sbn0 = sb[64 + j], sbn1 = sb[64 + j + 1];
      const float bir0 = sb[96 + j], bir1 = sb[96 + j + 1];
      const float biz0 = sb[96 + 32 + j], biz1 = sb[96 + 32 + j + 1];
      const float bin0 = sb[96 + 64 + j], bin1 = sb[96 + 64 + j + 1];
      const float wir0 = sb[192 + j], wir1 = sb[192 + j + 1];
      const float wiz0 = sb[192 + 32 + j], wiz1 = sb[192 + 32 + j + 1];
      const float win0 = sb[192 + 64 + j], win1 = sb[192 + 64 + j + 1];

      float onew[8];
#pragma unroll
      for (int mt = 0; mt < 2; ++mt) {
        const float xinA = sxin[mt * 16 + r0q];
        const float xinB = sxin[mt * 16 + r0q + 8];
#pragma unroll
        for (int half = 0; half < 2; ++half) {
          const float xin = half ? xinB : xinA;
          const int q0 = half * 2;
#pragma unroll
          for (int u = 0; u < 2; ++u) {
            const int hidx = mt * 4 + half * 2 + u;
            float gr = accR[mt][q0 + u] + (u ? sbr1 : sbr0) +
                       fmaf(xin, u ? wir1 : wir0, u ? bir1 : bir0);
            float gz = accZ[mt][q0 + u] + (u ? sbz1 : sbz0) +
                       fmaf(xin, u ? wiz1 : wiz0, u ? biz1 : biz0);
            float ghn = accN[mt][q0 + u] + (u ? sbn1 : sbn0);
            float gin = fmaf(xin, u ? win1 : win0, u ? bin1 : bin0);
            float r = sigmoid_fast(gr);
            float z = sigmoid_fast(gz);
            float n = tanh_fast(fmaf(r, ghn, gin));
            float hnew = fmaf(z, hreg[hidx] - n, n);
            hreg[hidx] = hnew;
            onew[hidx] = hnew;
          }
        }
      }
      // publish h' (fp16, one uint32 per (b, j-pair))
#pragma unroll
      for (int mt = 0; mt < 2; ++mt)
#pragma unroll
        for (int half = 0; half < 2; ++half) {
          const int hidx = mt * 4 + half * 2;
          const int b_glob = b0g + mt * 16 + r0q + 8 * half;
          uint32_t hv =
              (uint32_t)__half_as_ushort(__float2half_rn(onew[hidx])) |
              ((uint32_t)__half_as_ushort(__float2half_rn(onew[hidx + 1]))
               << 16);
          __stcg(reinterpret_cast<uint32_t*>(&g_h[d][nxt][b_glob][j0c + j]),
                 hv);
        }
      bar_sync(9, 128);  // all h' stores done
      if (tid == 0) cnt_bump(hcnt);
      // out stores (after bump; fire-and-forget)
#pragma unroll
      for (int mt = 0; mt < 2; ++mt)
#pragma unroll
        for (int half = 0; half < 2; ++half) {
          const int hidx = mt * 4 + half * 2;
          const int b_glob = b0g + mt * 16 + r0q + 8 * half;
          float2 ov = make_float2(onew[hidx], onew[hidx + 1]);
          *reinterpret_cast<float2*>(out + ((size_t)b_glob << 20) +
                                     ((size_t)pos << 10) + (d << 9) + j0c + j) =
              ov;
        }
    } else {
      // ================= staging warps 4-11 =================
      if (t > 0) {
        if (tid == 128) poll_ge(hcnt, (unsigned)(16 * t));
        bar_sync(5, 256);
      }
      {
        const uint4* hb4 = reinterpret_cast<const uint4*>(&g_h[d][cur][0][0]);
#pragma unroll
        for (int it = 0; it < 8; ++it) {
          const int task = it * 8 + sw;
          const int b = task >> 1;
          const int k16 = (task & 1) * 32 + lane;
          uint4 v = __ldcg(hb4 + (b0g + b) * 64 + k16);
          *reinterpret_cast<uint4*>(smem_c + kA + b * kRowB + k16 * 16) = v;
        }
      }
      bar_arrive(1, 384);

      if (sw == 0) {  // warp 4: compute sxin[32]
        const int b_glob = b0g + lane;
        float xv = __ldg(&x[(size_t)b_glob * kT + pos]);
        bool m;
        {
          const size_t midx = (size_t)b_glob * kT + pos;
          if (mmode == 1)
            m = ((const int*)mask)[midx] != 0;
          else if (mmode == 2)
            m = ((const float*)mask)[midx] != 0.f;
          else
            m = ((const uint8_t*)mask)[midx] != 0;
        }
        if (lane == 0) poll_ge(scnt, (unsigned)(16 * (t + 1)));
        __syncwarp();
        float a = 0.f;
        const float4* pp = reinterpret_cast<const float4*>(&g_spart[d][g][lane][0]);
#pragma unroll
        for (int q = 0; q < 4; ++q) {
          float4 v = __ldcg(pp + q);
          a += v.x + v.y + v.z + v.w;
        }
        const float scal = tanh_fast(a + sb[352]);
        sxin[lane] = m ? scal : xv;
      }
      bar_arrive(11, 384);  // sxin ready (warp4 arrives after its stores)
    }
    cur = nxt;
  }
}

extern "C" void kernel_launch(void* const* d_in, const int* in_sizes, int n_in,
                              void* d_out, int out_size) {
  const float* x = (const float*)d_in[0];
  const void* mask = (const void*)d_in[1];
  const float* wf_ih = (const float*)d_in[2];
  const float* wf_hh = (const float*)d_in[3];
  const float* bf_ih = (const float*)d_in[4];
  const float* bf_hh = (const float*)d_in[5];
  const float* wb_ih = (const float*)d_in[6];
  const float* wb_hh = (const float*)d_in[7];
  const float* bb_ih = (const float*)d_in[8];
  const float* bb_hh = (const float*)d_in[9];
  const float* p_w1 = (const float*)d_in[10];
  const float* p_b1 = (const float*)d_in[11];
  const float* p_w2 = (const float*)d_in[12];
  const float* p_b2 = (const float*)d_in[13];
  float* out = (float*)d_out;

  (void)in_sizes;
  (void)n_in;
  (void)out_size;

  cudaFuncSetAttribute(bidgru_kernel, cudaFuncAttributeMaxDynamicSharedMemorySize,
                       kSmemBytes);
  init_kernel<<<256, 256>>>(mask);
  bidgru_kernel<<<128, kThreads, kSmemBytes>>>(x, mask, wf_ih, wf_hh, bf_ih,
                                               bf_hh, wb_ih, wb_hh, bb_ih, bb_hh,
                                               p_w1, p_b1, p_w2, p_b2, out);
}